// round 3
// baseline (speedup 1.0000x reference)
#include <cuda_runtime.h>
#include <math.h>

#define B 64
#define S 512
#define H 1024
#define L 5

#define LOG2E_F 1.4426950408889634f
#define LN2_F   0.6931471805599453f

// Scratch (static device globals — allocation-free per harness rules)
__device__ float g_emis[B * S * L];
__device__ float g_num[B];
__device__ float g_logz[B];

__device__ __forceinline__ float ex2f_(float x) {
    float r; asm("ex2.approx.ftz.f32 %0, %1;" : "=f"(r) : "f"(x)); return r;
}
__device__ __forceinline__ float lg2f_(float x) {
    float r; asm("lg2.approx.f32 %0, %1;" : "=f"(r) : "f"(x)); return r;
}

// ---------------------------------------------------------------------------
// Kernel 1: emissions = relu(feats @ W + b)
// Thread owns 2 rows x 256 k (a quarter). W staged in shared, skewed so the
// 4 q-groups land on distinct banks (16-lane broadcast within a group).
// Reduction: only 2 shfl_xor levels (4 lanes per row-quarter group).
// 256 threads/block, 128 rows/block, 256 blocks.
// ---------------------------------------------------------------------------
__global__ __launch_bounds__(256) void k_emis(const float* __restrict__ feats,
                                              const float* __restrict__ Wg,
                                              const float* __restrict__ bias) {
    __shared__ float sW[8208];  // off(k) = k*8 + ((k>>8)<<2), elements 0..4 used
    const int t = threadIdx.x;
    for (int i = t; i < H * L; i += 256) {
        const int k = i / 5, l = i - k * 5;
        sW[k * 8 + ((k >> 8) << 2) + l] = Wg[i];
    }
    __syncthreads();

    const int lane = t & 31, w = t >> 5;
    const int q = lane & 3;       // k-quarter
    const int s = lane >> 2;      // row slot 0..7
    const int r0 = blockIdx.x * 128 + w * 16 + s;
    const int r1 = r0 + 8;
    const float4* p0 = (const float4*)(feats + (size_t)r0 * H + q * 256);
    const float4* p1 = (const float4*)(feats + (size_t)r1 * H + q * 256);

    float a0[5] = {0.f, 0.f, 0.f, 0.f, 0.f};
    float a1[5] = {0.f, 0.f, 0.f, 0.f, 0.f};
    const int kq = q * 256;

#pragma unroll 1
    for (int it = 0; it < 16; it++) {
        float4 x0[4], x1[4];
#pragma unroll
        for (int qq = 0; qq < 4; qq++) { x0[qq] = p0[it * 4 + qq]; x1[qq] = p1[it * 4 + qq]; }
#pragma unroll
        for (int qq = 0; qq < 4; qq++) {
            const int kb = kq + (it * 4 + qq) * 4;
#pragma unroll
            for (int e = 0; e < 4; e++) {
                const int k = kb + e;
                const int off = k * 8 + ((k >> 8) << 2);
                const float4 wv = *(const float4*)(sW + off);
                const float w4 = sW[off + 4];
                const float v0 = (e == 0) ? x0[qq].x : (e == 1) ? x0[qq].y
                               : (e == 2) ? x0[qq].z : x0[qq].w;
                const float v1 = (e == 0) ? x1[qq].x : (e == 1) ? x1[qq].y
                               : (e == 2) ? x1[qq].z : x1[qq].w;
                a0[0] = fmaf(v0, wv.x, a0[0]);
                a0[1] = fmaf(v0, wv.y, a0[1]);
                a0[2] = fmaf(v0, wv.z, a0[2]);
                a0[3] = fmaf(v0, wv.w, a0[3]);
                a0[4] = fmaf(v0, w4,   a0[4]);
                a1[0] = fmaf(v1, wv.x, a1[0]);
                a1[1] = fmaf(v1, wv.y, a1[1]);
                a1[2] = fmaf(v1, wv.z, a1[2]);
                a1[3] = fmaf(v1, wv.w, a1[3]);
                a1[4] = fmaf(v1, w4,   a1[4]);
            }
        }
    }

#pragma unroll
    for (int l = 0; l < 5; l++) {
        a0[l] += __shfl_xor_sync(0xffffffffu, a0[l], 1);
        a0[l] += __shfl_xor_sync(0xffffffffu, a0[l], 2);
        a1[l] += __shfl_xor_sync(0xffffffffu, a1[l], 1);
        a1[l] += __shfl_xor_sync(0xffffffffu, a1[l], 2);
    }
    if (q == 0) {
#pragma unroll
        for (int l = 0; l < 5; l++)
            g_emis[(size_t)r0 * 5 + l] = fmaxf(a0[l] + bias[l], 0.f);
    } else if (q == 1) {
#pragma unroll
        for (int l = 0; l < 5; l++)
            g_emis[(size_t)r1 * 5 + l] = fmaxf(a1[l] + bias[l], 0.f);
    }
}

// packed [5]->[5] map composition: returns f∘g (g applied first)
__device__ __forceinline__ int fcompose(int f, int g) {
    int r = 0;
#pragma unroll
    for (int x = 0; x < 5; x++) {
        int gx = (g >> (3 * x)) & 7;
        int fx = (f >> (3 * gx)) & 7;
        r |= fx << (3 * x);
    }
    return r;
}

// ---------------------------------------------------------------------------
// Kernel 2: per-batch CRF. One block per batch, 320 threads:
//   warps 0..7  : chunked forward scan (8 chunks of 64 steps, 25 lanes = 5x5
//                 transfer matrix in scaled-prob domain), warp 0 combines.
//   warp 8      : serial Viterbi (bit-exact to reference) + scan backtrace
//   warp 9      : gold-path numerator
// ---------------------------------------------------------------------------
__global__ __launch_bounds__(320) void k_crf(const int* __restrict__ labels,
                                             const float* __restrict__ start_tr,
                                             const float* __restrict__ end_tr,
                                             const float* __restrict__ trans,
                                             const float* __restrict__ wts,
                                             float* __restrict__ out) {
    const int b = blockIdx.x;
    const int tid = threadIdx.x;
    const int wid = tid >> 5;
    const int lane = tid & 31;
    const float* em = g_emis + (size_t)b * (S * L);

    __shared__ int   s_bp[S];
    __shared__ float sM[8 * 25];
    __shared__ int   sC[8];

    if (wid < 8) {
        // ============== forward: chunk transfer matrix (scaled prob) =======
        const int cj = lane % 5;        // column j
        const int ci = lane / 5;        // row i (>=5 for lanes 25..31)
        const bool act = lane < 25;
        const int b5 = lane - cj;       // 5*i
        const float E0 = ex2f_(trans[0 * L + cj] * LOG2E_F);
        const float E1 = ex2f_(trans[1 * L + cj] * LOG2E_F);
        const float E2 = ex2f_(trans[2 * L + cj] * LOG2E_F);
        const float E3 = ex2f_(trans[3 * L + cj] * LOG2E_F);
        const float E4 = ex2f_(trans[4 * L + cj] * LOG2E_F);

        float m = (act && ci == cj) ? 1.f : 0.f;
        int cexp = 0;
        const int t0 = 1 + 64 * wid;
        const int t1 = (t0 + 64 < S) ? (t0 + 64) : S;

        float fb[8];
#pragma unroll
        for (int u = 0; u < 8; u++) {
            int tt = t0 + u;
            fb[u] = (tt < t1) ? ex2f_(em[tt * 5 + cj] * LOG2E_F) : 1.f;
        }

        for (int tb = t0; tb < t1; tb += 8) {
            float fn[8];
#pragma unroll
            for (int u = 0; u < 8; u++) {
                int tt = tb + 8 + u;
                fn[u] = (tt < t1) ? ex2f_(em[tt * 5 + cj] * LOG2E_F) : 1.f;
            }
#pragma unroll
            for (int u = 0; u < 8; u++) {
                if (tb + u < t1) {
                    float a0 = __shfl_sync(0xffffffffu, m, b5 + 0);
                    float a1 = __shfl_sync(0xffffffffu, m, b5 + 1);
                    float a2 = __shfl_sync(0xffffffffu, m, b5 + 2);
                    float a3 = __shfl_sync(0xffffffffu, m, b5 + 3);
                    float a4 = __shfl_sync(0xffffffffu, m, b5 + 4);
                    float sm = (fmaf(a0, E0, a1 * E1) + fmaf(a2, E2, a3 * E3))
                               + a4 * E4;
                    m = act ? sm * fb[u] : 0.f;
                }
            }
            // renormalize by 2^-k, k = exponent of warp max
            float mx = m;
            mx = fmaxf(mx, __shfl_xor_sync(0xffffffffu, mx, 1));
            mx = fmaxf(mx, __shfl_xor_sync(0xffffffffu, mx, 2));
            mx = fmaxf(mx, __shfl_xor_sync(0xffffffffu, mx, 4));
            mx = fmaxf(mx, __shfl_xor_sync(0xffffffffu, mx, 8));
            mx = fmaxf(mx, __shfl_xor_sync(0xffffffffu, mx, 16));
            int kx = ((__float_as_int(mx) >> 23) & 255) - 127;
            m *= __int_as_float((127 - kx) << 23);
            cexp += kx;
#pragma unroll
            for (int u = 0; u < 8; u++) fb[u] = fn[u];
        }
        if (act) sM[wid * 25 + lane] = m;
        if (lane == 0) sC[wid] = cexp;
        asm volatile("bar.sync 1, 256;" ::: "memory");

        if (wid == 0) {
            // combine: v = alpha0; v <- v * M_c for c=0..7
            const bool aj = lane < 5;
            float v = aj ? ex2f_((start_tr[lane] + em[lane]) * LOG2E_F) : 0.f;
            int ct = 0;
#pragma unroll
            for (int c = 0; c < 8; c++) {
                float a0 = __shfl_sync(0xffffffffu, v, 0);
                float a1 = __shfl_sync(0xffffffffu, v, 1);
                float a2 = __shfl_sync(0xffffffffu, v, 2);
                float a3 = __shfl_sync(0xffffffffu, v, 3);
                float a4 = __shfl_sync(0xffffffffu, v, 4);
                float nv = 0.f;
                if (aj) {
                    const float* Mc = sM + c * 25 + lane;
                    nv = fmaf(a0, Mc[0], fmaf(a1, Mc[5], fmaf(a2, Mc[10],
                         fmaf(a3, Mc[15], a4 * Mc[20]))));
                }
                float mx = nv;
                mx = fmaxf(mx, __shfl_xor_sync(0xffffffffu, mx, 1));
                mx = fmaxf(mx, __shfl_xor_sync(0xffffffffu, mx, 2));
                mx = fmaxf(mx, __shfl_xor_sync(0xffffffffu, mx, 4));
                int kx = ((__float_as_int(mx) >> 23) & 255) - 127;
                v = nv * __int_as_float((127 - kx) << 23);
                ct += sC[c] + kx;
            }
            float r = aj ? v * ex2f_(end_tr[lane] * LOG2E_F) : 0.f;
            r += __shfl_xor_sync(0xffffffffu, r, 1);
            r += __shfl_xor_sync(0xffffffffu, r, 2);
            r += __shfl_xor_sync(0xffffffffu, r, 4);
            if (lane == 0)
                g_logz[b] = ((float)ct + lg2f_(fmaxf(r, 1e-38f))) * LN2_F;
        }
    } else if (wid == 8) {
        // ========================== Viterbi (serial, bit-exact) ============
        const bool act = lane < L;
        const int j = lane;
        float T0 = 0.f, T1 = 0.f, T2 = 0.f, T3 = 0.f, T4 = 0.f;
        float v = -1e30f;
        if (act) {
            T0 = trans[0 * L + j];
            T1 = trans[1 * L + j];
            T2 = trans[2 * L + j];
            T3 = trans[3 * L + j];
            T4 = trans[4 * L + j];
            v = start_tr[j] + em[j];
        }

        float eb[8];
#pragma unroll
        for (int u = 0; u < 8; u++)
            eb[u] = act ? em[(1 + u) * L + j] : 0.f;

        for (int tb = 1; tb < S; tb += 8) {
            float en[8];
#pragma unroll
            for (int u = 0; u < 8; u++) {
                int tt = tb + 8 + u;
                en[u] = (act && tt < S) ? em[tt * L + j] : 0.f;
            }
#pragma unroll
            for (int u = 0; u < 8; u++) {
                int tcur = tb + u;
                if (tcur < S) {
                    float v0 = __shfl_sync(0xffffffffu, v, 0);
                    float v1 = __shfl_sync(0xffffffffu, v, 1);
                    float v2 = __shfl_sync(0xffffffffu, v, 2);
                    float v3 = __shfl_sync(0xffffffffu, v, 3);
                    float v4 = __shfl_sync(0xffffffffu, v, 4);
                    float c0 = v0 + T0, c1 = v1 + T1, c2 = v2 + T2;
                    float c3 = v3 + T3, c4 = v4 + T4;
                    float best = fmaxf(fmaxf(fmaxf(c0, c1), fmaxf(c2, c3)), c4);
                    // first-occurrence argmax (ties -> lowest index)
                    int bp = (c0 == best) ? 0 : (c1 == best) ? 1
                           : (c2 == best) ? 2 : (c3 == best) ? 3 : 4;
                    v = act ? (best + eb[u]) : -1e30f;
                    unsigned pk = __reduce_add_sync(0xffffffffu,
                                  act ? ((unsigned)bp << (3 * j)) : 0u);
                    if (lane == 0) s_bp[tcur] = (int)pk;
                }
            }
#pragma unroll
            for (int u = 0; u < 8; u++) eb[u] = en[u];
        }

        // final tag: first-occurrence argmax over (v + end)
        float sc = act ? (v + end_tr[j]) : -1e30f;
        float s0 = __shfl_sync(0xffffffffu, sc, 0);
        float s1 = __shfl_sync(0xffffffffu, sc, 1);
        float s2 = __shfl_sync(0xffffffffu, sc, 2);
        float s3 = __shfl_sync(0xffffffffu, sc, 3);
        float s4 = __shfl_sync(0xffffffffu, sc, 4);
        int last = 0; float bb = s0;
        if (s1 > bb) { bb = s1; last = 1; }
        if (s2 > bb) { bb = s2; last = 2; }
        if (s3 > bb) { bb = s3; last = 3; }
        if (s4 > bb) { bb = s4; last = 4; }

        __syncwarp(0xffffffffu);

        // backtrace via suffix scan of packed [5]->[5] map compositions
        const int IDMAP = 0 | (1 << 3) | (2 << 6) | (3 << 9) | (4 << 12);
        int wv[16];
        const int tb2 = lane * 16;
#pragma unroll
        for (int u = 0; u < 16; u++) wv[u] = s_bp[tb2 + u];
        if (lane == 0) wv[0] = IDMAP;

        int G = wv[0];
#pragma unroll
        for (int u = 1; u < 16; u++) G = fcompose(G, wv[u]);

        int T = G;
#pragma unroll
        for (int d = 1; d < 32; d <<= 1) {
            int o = __shfl_down_sync(0xffffffffu, T, d);
            T = (lane + d < 32) ? fcompose(T, o) : T;
        }
        int E = __shfl_down_sync(0xffffffffu, T, 1);
        if (lane == 31) E = IDMAP;

        int tag = (E >> (3 * last)) & 7;
        float* po = out + 1 + (size_t)b * S;
        po[tb2 + 15] = (float)tag;
#pragma unroll
        for (int u = 15; u >= 1; u--) {
            tag = (wv[u] >> (3 * tag)) & 7;
            po[tb2 + u - 1] = (float)tag;
        }
    } else {
        // ========================== numerator ==============================
        const int* lb = labels + b * S;
        float acc = 0.f;
        for (int s2 = lane; s2 < S; s2 += 32) {
            int l0 = lb[s2];
            float term = wts[l0] * em[s2 * L + l0];
            if (s2 + 1 < S) {
                int l1 = lb[s2 + 1];
                term += trans[l0 * L + l1];
            }
            acc += term;
        }
#pragma unroll
        for (int d = 16; d > 0; d >>= 1)
            acc += __shfl_xor_sync(0xffffffffu, acc, d);
        if (lane == 0)
            g_num[b] = acc + start_tr[lb[0]] + end_tr[lb[S - 1]];
    }
}

// ---------------------------------------------------------------------------
// Kernel 3: loss = -sum_b(num_b - logz_b) / (B*S)
// ---------------------------------------------------------------------------
__global__ __launch_bounds__(64) void k_final(float* __restrict__ out) {
    const int t = threadIdx.x;
    float v = g_num[t] - g_logz[t];
#pragma unroll
    for (int d = 16; d > 0; d >>= 1)
        v += __shfl_xor_sync(0xffffffffu, v, d);
    __shared__ float sh[2];
    if ((t & 31) == 0) sh[t >> 5] = v;
    __syncthreads();
    if (t == 0) out[0] = -(sh[0] + sh[1]) * (1.0f / (float)(B * S));
}

// ---------------------------------------------------------------------------
// Launch. Inputs: feats f32, labels i32, mask bool (all ones, unused),
// W_tag f32, b_tag f32, start_trans f32, end_trans f32, trans f32, weights f32.
// Output: [loss, paths(B*S)] as float32.
// ---------------------------------------------------------------------------
extern "C" void kernel_launch(void* const* d_in, const int* in_sizes, int n_in,
                              void* d_out, int out_size) {
    (void)in_sizes; (void)n_in; (void)out_size;
    const float* feats  = (const float*)d_in[0];
    const int*   labels = (const int*)d_in[1];
    const float* W      = (const float*)d_in[3];
    const float* bias   = (const float*)d_in[4];
    const float* st     = (const float*)d_in[5];
    const float* en     = (const float*)d_in[6];
    const float* tr     = (const float*)d_in[7];
    const float* wt     = (const float*)d_in[8];
    float* out = (float*)d_out;

    k_emis<<<256, 256>>>(feats, W, bias);
    k_crf<<<B, 320>>>(labels, st, en, tr, wt, out);
    k_final<<<1, 64>>>(out);
}

// round 6
// speedup vs baseline: 1.0957x; 1.0957x over previous
#include <cuda_runtime.h>
#include <math.h>

#define B 64
#define S 512
#define H 1024
#define L 5

#define LOG2E_F 1.4426950408889634f
#define LN2_F   0.6931471805599453f

// Scratch (static device globals — allocation-free per harness rules)
__device__ float g_emis[B * S * L];
__device__ float g_num[B];
__device__ float g_logz[B];

__device__ __forceinline__ float ex2f_(float x) {
    float r; asm("ex2.approx.ftz.f32 %0, %1;" : "=f"(r) : "f"(x)); return r;
}
__device__ __forceinline__ float lg2f_(float x) {
    float r; asm("lg2.approx.f32 %0, %1;" : "=f"(r) : "f"(x)); return r;
}

// ---------------------------------------------------------------------------
// Kernel 1: emissions = relu(feats @ W + b)
// One thread per (row, k-quarter). Thread streams 64 float4 of its row quarter
// (L1-resident lines, double-buffered 4-wide for MLP). W comes from smem via
// broadcast LDS.128 (4 distinct addrs/instr on disjoint bank quads via +4f
// per-quarter skew). Reduction: 2 shfl levels over the 4 quarter-lanes.
// grid 1024 x 128 threads; 32 rows per block.
// ---------------------------------------------------------------------------
__global__ __launch_bounds__(128) void k_emis(const float* __restrict__ feats,
                                              const float* __restrict__ Wg,
                                              const float* __restrict__ bias) {
    // layout: addr(g,e) = (g>>6)*1284 + (g&63)*20 + e,  g = k/4 (0..255), e 0..19
    __shared__ float sW[4 * 1284];
    const int t = threadIdx.x;
    for (int i = t; i < H * L; i += 128) {
        const int g = i / 20, e = i - g * 20;
        sW[(g >> 6) * 1284 + (g & 63) * 20 + e] = Wg[i];
    }
    __syncthreads();

    const int lane = t & 31, w = t >> 5;
    const int q = lane & 3;        // k-quarter
    const int s = lane >> 2;       // row slot 0..7
    const int row = blockIdx.x * 32 + w * 8 + s;
    const float4* fp = (const float4*)(feats + (size_t)row * H) + q * 64;
    const float* wq = sW + q * 1284;

    float a0 = 0.f, a1 = 0.f, a2 = 0.f, a3 = 0.f, a4 = 0.f;

    float4 xa[4];
#pragma unroll
    for (int u = 0; u < 4; u++) xa[u] = fp[u];

#pragma unroll 1
    for (int it0 = 0; it0 < 64; it0 += 4) {
        float4 xb[4];
        if (it0 + 4 < 64) {
#pragma unroll
            for (int u = 0; u < 4; u++) xb[u] = fp[it0 + 4 + u];
        }
#pragma unroll
        for (int u = 0; u < 4; u++) {
            const float* wp = wq + (it0 + u) * 20;
            const float4 wa = *(const float4*)(wp);
            const float4 wb = *(const float4*)(wp + 4);
            const float4 wc = *(const float4*)(wp + 8);
            const float4 wd = *(const float4*)(wp + 12);
            const float4 we = *(const float4*)(wp + 16);
            const float4 x = xa[u];
            // W[k][l] row-major, group covers k0..k0+3
            a0 = fmaf(x.x, wa.x, fmaf(x.y, wb.y, fmaf(x.z, wc.z, fmaf(x.w, wd.w, a0))));
            a1 = fmaf(x.x, wa.y, fmaf(x.y, wb.z, fmaf(x.z, wc.w, fmaf(x.w, we.x, a1))));
            a2 = fmaf(x.x, wa.z, fmaf(x.y, wb.w, fmaf(x.z, wd.x, fmaf(x.w, we.y, a2))));
            a3 = fmaf(x.x, wa.w, fmaf(x.y, wc.x, fmaf(x.z, wd.y, fmaf(x.w, we.z, a3))));
            a4 = fmaf(x.x, wb.x, fmaf(x.y, wc.y, fmaf(x.z, wd.z, fmaf(x.w, we.w, a4))));
        }
#pragma unroll
        for (int u = 0; u < 4; u++) xa[u] = xb[u];
    }

    // reduce over the 4 quarter-lanes (xor 1, 2)
    a0 += __shfl_xor_sync(0xffffffffu, a0, 1);
    a1 += __shfl_xor_sync(0xffffffffu, a1, 1);
    a2 += __shfl_xor_sync(0xffffffffu, a2, 1);
    a3 += __shfl_xor_sync(0xffffffffu, a3, 1);
    a4 += __shfl_xor_sync(0xffffffffu, a4, 1);
    a0 += __shfl_xor_sync(0xffffffffu, a0, 2);
    a1 += __shfl_xor_sync(0xffffffffu, a1, 2);
    a2 += __shfl_xor_sync(0xffffffffu, a2, 2);
    a3 += __shfl_xor_sync(0xffffffffu, a3, 2);
    a4 += __shfl_xor_sync(0xffffffffu, a4, 2);

    if (q == 0) {
        float* o = g_emis + (size_t)row * 5;
        o[0] = fmaxf(a0 + bias[0], 0.f);
        o[1] = fmaxf(a1 + bias[1], 0.f);
        o[2] = fmaxf(a2 + bias[2], 0.f);
        o[3] = fmaxf(a3 + bias[3], 0.f);
        o[4] = fmaxf(a4 + bias[4], 0.f);
    }
}

// packed [5]->[5] map composition: returns f∘g (g applied first)
__device__ __forceinline__ int fcompose(int f, int g) {
    int r = 0;
#pragma unroll
    for (int x = 0; x < 5; x++) {
        int gx = (g >> (3 * x)) & 7;
        int fx = (f >> (3 * gx)) & 7;
        r |= fx << (3 * x);
    }
    return r;
}

// ---------------------------------------------------------------------------
// Kernel 2: CRF. Grid = 128 blocks (one wave, each on its own SM):
//   blocks 0..63   : serial bit-exact Viterbi for batch b (warp 0 only,
//                    isolated — no issue/MIO contention on its SM)
//   blocks 64..127 : chunked forward scan (warps 0..7) + numerator (warp 8)
// ---------------------------------------------------------------------------
__global__ __launch_bounds__(288) void k_crf(const int* __restrict__ labels,
                                             const float* __restrict__ start_tr,
                                             const float* __restrict__ end_tr,
                                             const float* __restrict__ trans,
                                             const float* __restrict__ wts,
                                             float* __restrict__ out) {
    const int bid = blockIdx.x;
    const int tid = threadIdx.x;
    const int wid = tid >> 5;
    const int lane = tid & 31;

    if (bid < 64) {
        // ==================== Viterbi (serial, bit-exact) ===================
        if (wid != 0) return;
        const int b = bid;
        const float* em = g_emis + (size_t)b * (S * L);
        __shared__ int s_bp[S];

        const bool act = lane < L;
        const int j = lane;
        float T0 = 0.f, T1 = 0.f, T2 = 0.f, T3 = 0.f, T4 = 0.f;
        float v = -1e30f;
        if (act) {
            T0 = trans[0 * L + j];
            T1 = trans[1 * L + j];
            T2 = trans[2 * L + j];
            T3 = trans[3 * L + j];
            T4 = trans[4 * L + j];
            v = start_tr[j] + em[j];
        }

        float eb[8];
#pragma unroll
        for (int u = 0; u < 8; u++)
            eb[u] = act ? em[(1 + u) * L + j] : 0.f;

        for (int tb = 1; tb < S; tb += 8) {
            float en[8];
#pragma unroll
            for (int u = 0; u < 8; u++) {
                int tt = tb + 8 + u;
                en[u] = (act && tt < S) ? em[tt * L + j] : 0.f;
            }
#pragma unroll
            for (int u = 0; u < 8; u++) {
                int tcur = tb + u;
                if (tcur < S) {
                    float v0 = __shfl_sync(0xffffffffu, v, 0);
                    float v1 = __shfl_sync(0xffffffffu, v, 1);
                    float v2 = __shfl_sync(0xffffffffu, v, 2);
                    float v3 = __shfl_sync(0xffffffffu, v, 3);
                    float v4 = __shfl_sync(0xffffffffu, v, 4);
                    float c0 = v0 + T0, c1 = v1 + T1, c2 = v2 + T2;
                    float c3 = v3 + T3, c4 = v4 + T4;
                    float b01 = fmaxf(c0, c1), b23 = fmaxf(c2, c3);
                    float best = fmaxf(fmaxf(b01, b23), c4);
                    // first-occurrence argmax (ties -> lowest index), off-path
                    int bp = (c0 == best) ? 0 : (c1 == best) ? 1
                           : (c2 == best) ? 2 : (c3 == best) ? 3 : 4;
                    v = act ? (best + eb[u]) : -1e30f;
                    unsigned pk = __reduce_add_sync(0xffffffffu,
                                  act ? ((unsigned)bp << (3 * j)) : 0u);
                    if (lane == 0) s_bp[tcur] = (int)pk;
                }
            }
#pragma unroll
            for (int u = 0; u < 8; u++) eb[u] = en[u];
        }

        // final tag: first-occurrence argmax over (v + end)
        float sc = act ? (v + end_tr[j]) : -1e30f;
        float s0 = __shfl_sync(0xffffffffu, sc, 0);
        float s1 = __shfl_sync(0xffffffffu, sc, 1);
        float s2 = __shfl_sync(0xffffffffu, sc, 2);
        float s3 = __shfl_sync(0xffffffffu, sc, 3);
        float s4 = __shfl_sync(0xffffffffu, sc, 4);
        int last = 0; float bb = s0;
        if (s1 > bb) { bb = s1; last = 1; }
        if (s2 > bb) { bb = s2; last = 2; }
        if (s3 > bb) { bb = s3; last = 3; }
        if (s4 > bb) { bb = s4; last = 4; }

        __syncwarp(0xffffffffu);

        // backtrace via suffix scan of packed [5]->[5] map compositions
        const int IDMAP = 0 | (1 << 3) | (2 << 6) | (3 << 9) | (4 << 12);
        int wv[16];
        const int tb2 = lane * 16;
#pragma unroll
        for (int u = 0; u < 16; u++) wv[u] = s_bp[tb2 + u];
        if (lane == 0) wv[0] = IDMAP;

        int G = wv[0];
#pragma unroll
        for (int u = 1; u < 16; u++) G = fcompose(G, wv[u]);

        int T = G;
#pragma unroll
        for (int d = 1; d < 32; d <<= 1) {
            int o = __shfl_down_sync(0xffffffffu, T, d);
            T = (lane + d < 32) ? fcompose(T, o) : T;
        }
        int E = __shfl_down_sync(0xffffffffu, T, 1);
        if (lane == 31) E = IDMAP;

        int tag = (E >> (3 * last)) & 7;
        float* po = out + 1 + (size_t)b * S;
        po[tb2 + 15] = (float)tag;
#pragma unroll
        for (int u = 15; u >= 1; u--) {
            tag = (wv[u] >> (3 * tag)) & 7;
            po[tb2 + u - 1] = (float)tag;
        }
        return;
    }

    // ======================= forward + numerator ===========================
    const int b = bid - 64;
    const float* em = g_emis + (size_t)b * (S * L);
    __shared__ float sM[8 * 25];
    __shared__ int   sC[8];

    if (wid < 8) {
        // ============== forward: chunk transfer matrix (scaled prob) =======
        const int cj = lane % 5;        // column j
        const int ci = lane / 5;        // row i (>=5 for lanes 25..31)
        const bool act = lane < 25;
        const int b5 = lane - cj;       // 5*i
        const float E0 = ex2f_(trans[0 * L + cj] * LOG2E_F);
        const float E1 = ex2f_(trans[1 * L + cj] * LOG2E_F);
        const float E2 = ex2f_(trans[2 * L + cj] * LOG2E_F);
        const float E3 = ex2f_(trans[3 * L + cj] * LOG2E_F);
        const float E4 = ex2f_(trans[4 * L + cj] * LOG2E_F);

        float m = (act && ci == cj) ? 1.f : 0.f;
        int cexp = 0;
        const int t0 = 1 + 64 * wid;
        const int t1 = (t0 + 64 < S) ? (t0 + 64) : S;

        float fb[8];
#pragma unroll
        for (int u = 0; u < 8; u++) {
            int tt = t0 + u;
            fb[u] = (tt < t1) ? ex2f_(em[tt * 5 + cj] * LOG2E_F) : 1.f;
        }

        for (int tb = t0; tb < t1; tb += 8) {
            float fn[8];
#pragma unroll
            for (int u = 0; u < 8; u++) {
                int tt = tb + 8 + u;
                fn[u] = (tt < t1) ? ex2f_(em[tt * 5 + cj] * LOG2E_F) : 1.f;
            }
#pragma unroll
            for (int u = 0; u < 8; u++) {
                if (tb + u < t1) {
                    float a0 = __shfl_sync(0xffffffffu, m, b5 + 0);
                    float a1 = __shfl_sync(0xffffffffu, m, b5 + 1);
                    float a2 = __shfl_sync(0xffffffffu, m, b5 + 2);
                    float a3 = __shfl_sync(0xffffffffu, m, b5 + 3);
                    float a4 = __shfl_sync(0xffffffffu, m, b5 + 4);
                    float sm = (fmaf(a0, E0, a1 * E1) + fmaf(a2, E2, a3 * E3))
                               + a4 * E4;
                    m = act ? sm * fb[u] : 0.f;
                }
            }
            // renormalize by 2^-k, k = exponent of warp max
            float mx = m;
            mx = fmaxf(mx, __shfl_xor_sync(0xffffffffu, mx, 1));
            mx = fmaxf(mx, __shfl_xor_sync(0xffffffffu, mx, 2));
            mx = fmaxf(mx, __shfl_xor_sync(0xffffffffu, mx, 4));
            mx = fmaxf(mx, __shfl_xor_sync(0xffffffffu, mx, 8));
            mx = fmaxf(mx, __shfl_xor_sync(0xffffffffu, mx, 16));
            int kx = ((__float_as_int(mx) >> 23) & 255) - 127;
            m *= __int_as_float((127 - kx) << 23);
            cexp += kx;
#pragma unroll
            for (int u = 0; u < 8; u++) fb[u] = fn[u];
        }
        if (act) sM[wid * 25 + lane] = m;
        if (lane == 0) sC[wid] = cexp;
        asm volatile("bar.sync 1, 256;" ::: "memory");

        if (wid == 0) {
            // combine: v = alpha0; v <- v * M_c for c=0..7
            const bool aj = lane < 5;
            float v = aj ? ex2f_((start_tr[lane] + em[lane]) * LOG2E_F) : 0.f;
            int ct = 0;
#pragma unroll
            for (int c = 0; c < 8; c++) {
                float a0 = __shfl_sync(0xffffffffu, v, 0);
                float a1 = __shfl_sync(0xffffffffu, v, 1);
                float a2 = __shfl_sync(0xffffffffu, v, 2);
                float a3 = __shfl_sync(0xffffffffu, v, 3);
                float a4 = __shfl_sync(0xffffffffu, v, 4);
                float nv = 0.f;
                if (aj) {
                    const float* Mc = sM + c * 25 + lane;
                    nv = fmaf(a0, Mc[0], fmaf(a1, Mc[5], fmaf(a2, Mc[10],
                         fmaf(a3, Mc[15], a4 * Mc[20]))));
                }
                float mx = nv;
                mx = fmaxf(mx, __shfl_xor_sync(0xffffffffu, mx, 1));
                mx = fmaxf(mx, __shfl_xor_sync(0xffffffffu, mx, 2));
                mx = fmaxf(mx, __shfl_xor_sync(0xffffffffu, mx, 4));
                int kx = ((__float_as_int(mx) >> 23) & 255) - 127;
                v = nv * __int_as_float((127 - kx) << 23);
                ct += sC[c] + kx;
            }
            float r = aj ? v * ex2f_(end_tr[lane] * LOG2E_F) : 0.f;
            r += __shfl_xor_sync(0xffffffffu, r, 1);
            r += __shfl_xor_sync(0xffffffffu, r, 2);
            r += __shfl_xor_sync(0xffffffffu, r, 4);
            if (lane == 0)
                g_logz[b] = ((float)ct + lg2f_(fmaxf(r, 1e-38f))) * LN2_F;
        }
    } else if (wid == 8) {
        // ========================== numerator ==============================
        const int* lb = labels + b * S;
        float acc = 0.f;
        for (int s2 = lane; s2 < S; s2 += 32) {
            int l0 = lb[s2];
            float term = wts[l0] * em[s2 * L + l0];
            if (s2 + 1 < S) {
                int l1 = lb[s2 + 1];
                term += trans[l0 * L + l1];
            }
            acc += term;
        }
#pragma unroll
        for (int d = 16; d > 0; d >>= 1)
            acc += __shfl_xor_sync(0xffffffffu, acc, d);
        if (lane == 0)
            g_num[b] = acc + start_tr[lb[0]] + end_tr[lb[S - 1]];
    }
}

// ---------------------------------------------------------------------------
// Kernel 3: loss = -sum_b(num_b - logz_b) / (B*S)
// ---------------------------------------------------------------------------
__global__ __launch_bounds__(64) void k_final(float* __restrict__ out) {
    const int t = threadIdx.x;
    float v = g_num[t] - g_logz[t];
#pragma unroll
    for (int d = 16; d > 0; d >>= 1)
        v += __shfl_xor_sync(0xffffffffu, v, d);
    __shared__ float sh[2];
    if ((t & 31) == 0) sh[t >> 5] = v;
    __syncthreads();
    if (t == 0) out[0] = -(sh[0] + sh[1]) * (1.0f / (float)(B * S));
}

// ---------------------------------------------------------------------------
// Launch. Inputs: feats f32, labels i32, mask bool (all ones, unused),
// W_tag f32, b_tag f32, start_trans f32, end_trans f32, trans f32, weights f32.
// Output: [loss, paths(B*S)] as float32.
// ---------------------------------------------------------------------------
extern "C" void kernel_launch(void* const* d_in, const int* in_sizes, int n_in,
                              void* d_out, int out_size) {
    (void)in_sizes; (void)n_in; (void)out_size;
    const float* feats  = (const float*)d_in[0];
    const int*   labels = (const int*)d_in[1];
    const float* W      = (const float*)d_in[3];
    const float* bias   = (const float*)d_in[4];
    const float* st     = (const float*)d_in[5];
    const float* en     = (const float*)d_in[6];
    const float* tr     = (const float*)d_in[7];
    const float* wt     = (const float*)d_in[8];
    float* out = (float*)d_out;

    k_emis<<<1024, 128>>>(feats, W, bias);
    k_crf<<<128, 288>>>(labels, st, en, tr, wt, out);
    k_final<<<1, 64>>>(out);
}

// round 10
// speedup vs baseline: 1.5371x; 1.4029x over previous
#include <cuda_runtime.h>
#include <math.h>

#define B 64
#define S 512
#define H 1024
#define L 5

#define LOG2E_F 1.4426950408889634f
#define LN2_F   0.6931471805599453f

// Scratch (static device globals — allocation-free per harness rules)
__device__ float g_emis[B * S * L];
__device__ float g_num[B];
__device__ float g_logz[B];

__device__ __forceinline__ float ex2f_(float x) {
    float r; asm("ex2.approx.ftz.f32 %0, %1;" : "=f"(r) : "f"(x)); return r;
}
__device__ __forceinline__ float lg2f_(float x) {
    float r; asm("lg2.approx.f32 %0, %1;" : "=f"(r) : "f"(x)); return r;
}

__device__ __forceinline__ void dot4(float& a, const float4& v, const float4& wv) {
    a = fmaf(v.x, wv.x, fmaf(v.y, wv.y, fmaf(v.z, wv.z, fmaf(v.w, wv.w, a))));
}

// ---------------------------------------------------------------------------
// Kernel 1: emissions = relu(feats @ W + b)
// Warp owns 4 rows. Lane owns float4 k-slice (lane + 32*i): every LDG.128 is
// a contiguous 512B warp read (4 L1 wavefronts, the floor). W is transposed
// in smem sWT[l][k] so LDS.128 is stride-16B across lanes (conflict-free).
// Epilogue: 5-stage butterfly over 20 accs, lanes 0..19 write contiguously.
// 1024 blocks x 256 threads (8 warps x 4 rows = 32 rows/block).
// ---------------------------------------------------------------------------
__global__ __launch_bounds__(256) void k_emis(const float* __restrict__ feats,
                                              const float* __restrict__ Wg,
                                              const float* __restrict__ bias) {
    __shared__ float sWT[5 * 1024];   // sWT[l*1024 + k] = W[k][l]
    const int t = threadIdx.x;
    for (int i = t; i < H * L; i += 256) {
        const int k = i / 5, l = i - 5 * k;
        sWT[l * 1024 + k] = Wg[i];
    }
    __syncthreads();

    const int lane = t & 31, w = t >> 5;
    const int row0 = blockIdx.x * 32 + w * 4;
    const float4* p0 = (const float4*)(feats + (size_t)(row0 + 0) * H);
    const float4* p1 = (const float4*)(feats + (size_t)(row0 + 1) * H);
    const float4* p2 = (const float4*)(feats + (size_t)(row0 + 2) * H);
    const float4* p3 = (const float4*)(feats + (size_t)(row0 + 3) * H);

    float acc[4][5];
#pragma unroll
    for (int r = 0; r < 4; r++)
#pragma unroll
        for (int l = 0; l < 5; l++) acc[r][l] = 0.f;

    float4 xa0 = p0[lane], xa1 = p1[lane], xa2 = p2[lane], xa3 = p3[lane];

#pragma unroll
    for (int i = 0; i < 8; i++) {
        float4 xb0, xb1, xb2, xb3;
        if (i < 7) {
            const int idx = lane + 32 * (i + 1);
            xb0 = p0[idx]; xb1 = p1[idx]; xb2 = p2[idx]; xb3 = p3[idx];
        }
        const int ko = (lane + 32 * i) * 4;
        const float4 w0 = *(const float4*)(sWT + 0 * 1024 + ko);
        const float4 w1 = *(const float4*)(sWT + 1 * 1024 + ko);
        const float4 w2 = *(const float4*)(sWT + 2 * 1024 + ko);
        const float4 w3 = *(const float4*)(sWT + 3 * 1024 + ko);
        const float4 w4 = *(const float4*)(sWT + 4 * 1024 + ko);

        dot4(acc[0][0], xa0, w0); dot4(acc[0][1], xa0, w1);
        dot4(acc[0][2], xa0, w2); dot4(acc[0][3], xa0, w3);
        dot4(acc[0][4], xa0, w4);
        dot4(acc[1][0], xa1, w0); dot4(acc[1][1], xa1, w1);
        dot4(acc[1][2], xa1, w2); dot4(acc[1][3], xa1, w3);
        dot4(acc[1][4], xa1, w4);
        dot4(acc[2][0], xa2, w0); dot4(acc[2][1], xa2, w1);
        dot4(acc[2][2], xa2, w2); dot4(acc[2][3], xa2, w3);
        dot4(acc[2][4], xa2, w4);
        dot4(acc[3][0], xa3, w0); dot4(acc[3][1], xa3, w1);
        dot4(acc[3][2], xa3, w2); dot4(acc[3][3], xa3, w3);
        dot4(acc[3][4], xa3, w4);

        if (i < 7) { xa0 = xb0; xa1 = xb1; xa2 = xb2; xa3 = xb3; }
    }

    // butterfly reduce all 20 accumulators over the 32 lanes
#pragma unroll
    for (int r = 0; r < 4; r++)
#pragma unroll
        for (int l = 0; l < 5; l++) {
#pragma unroll
            for (int d = 16; d > 0; d >>= 1)
                acc[r][l] += __shfl_xor_sync(0xffffffffu, acc[r][l], d);
        }

    // lane m (< 20) writes output element row0*5 + m  (m = r*5 + l)
    float val = 0.f;
#pragma unroll
    for (int r = 0; r < 4; r++)
#pragma unroll
        for (int l = 0; l < 5; l++)
            if (lane == r * 5 + l) val = acc[r][l];
    if (lane < 20)
        g_emis[(size_t)row0 * 5 + lane] = fmaxf(val + bias[lane % 5], 0.f);
}

// packed [5]->[5] map composition: returns f∘g (g applied first)
__device__ __forceinline__ int fcompose(int f, int g) {
    int r = 0;
#pragma unroll
    for (int x = 0; x < 5; x++) {
        int gx = (g >> (3 * x)) & 7;
        int fx = (f >> (3 * gx)) & 7;
        r |= fx << (3 * x);
    }
    return r;
}

// ---------------------------------------------------------------------------
// Kernel 2: CRF. One block per batch, 320 threads (10 warps):
//   warp 8   : pass-A Viterbi (value-only, bit-exact serial recurrence),
//              stores exact chunk-boundary vectors every 64 steps; then after
//              bar3, the compose-scan backtrace.
//   warps0-7 : forward chunk transfer matrices (scaled prob) -> bar1 ->
//              warp0 combine (logZ) -> bar2 (wait pass-A boundaries) ->
//              pass-B Viterbi chunk (64 steps with backpointers) -> bar3.
//   warp 9   : gold-path numerator.
// ---------------------------------------------------------------------------
__global__ __launch_bounds__(320) void k_crf(const int* __restrict__ labels,
                                             const float* __restrict__ start_tr,
                                             const float* __restrict__ end_tr,
                                             const float* __restrict__ trans,
                                             const float* __restrict__ wts,
                                             float* __restrict__ out) {
    const int b = blockIdx.x;
    const int tid = threadIdx.x;
    const int wid = tid >> 5;
    const int lane = tid & 31;
    const float* em = g_emis + (size_t)b * (S * L);

    __shared__ int   s_bp[S];
    __shared__ float sM[8 * 25];
    __shared__ int   sC[8];
    __shared__ float sBnd[8 * 5];   // exact Viterbi state at t = 64*c

    if (wid == 8) {
        // ================= pass A: value-only Viterbi (serial) =============
        const int j = lane % 5;     // lanes mirror tags; lanes 0..4 canonical
        const float T0 = trans[0 * L + j];
        const float T1 = trans[1 * L + j];
        const float T2 = trans[2 * L + j];
        const float T3 = trans[3 * L + j];
        const float T4 = trans[4 * L + j];
        float v = start_tr[j] + em[j];
        if (lane < 5) sBnd[lane] = v;   // boundary c=0 (t=0)

        float eb[8];
#pragma unroll
        for (int u = 0; u < 8; u++) eb[u] = em[(1 + u) * 5 + j];

        for (int tb = 1; tb < S; tb += 8) {
            float en[8];
#pragma unroll
            for (int u = 0; u < 8; u++) {
                int tt = tb + 8 + u;
                en[u] = (tt < S) ? em[tt * 5 + j] : 0.f;
            }
#pragma unroll
            for (int u = 0; u < 8; u++) {
                const int tcur = tb + u;
                if (tcur < S) {
                    float v0 = __shfl_sync(0xffffffffu, v, 0);
                    float v1 = __shfl_sync(0xffffffffu, v, 1);
                    float v2 = __shfl_sync(0xffffffffu, v, 2);
                    float v3 = __shfl_sync(0xffffffffu, v, 3);
                    float v4 = __shfl_sync(0xffffffffu, v, 4);
                    float c0 = v0 + T0, c1 = v1 + T1, c2 = v2 + T2;
                    float c3 = v3 + T3, c4 = v4 + T4;
                    float best = fmaxf(fmaxf(fmaxf(c0, c1), fmaxf(c2, c3)), c4);
                    v = best + eb[u];
                    if (((tcur & 63) == 0) && lane < 5)
                        sBnd[(tcur >> 6) * 5 + lane] = v;
                }
            }
#pragma unroll
            for (int u = 0; u < 8; u++) eb[u] = en[u];
        }

        // final tag: first-occurrence argmax over (v + end)
        float sc = v + end_tr[j];
        float s0 = __shfl_sync(0xffffffffu, sc, 0);
        float s1 = __shfl_sync(0xffffffffu, sc, 1);
        float s2 = __shfl_sync(0xffffffffu, sc, 2);
        float s3 = __shfl_sync(0xffffffffu, sc, 3);
        float s4 = __shfl_sync(0xffffffffu, sc, 4);
        int last = 0; float bb = s0;
        if (s1 > bb) { bb = s1; last = 1; }
        if (s2 > bb) { bb = s2; last = 2; }
        if (s3 > bb) { bb = s3; last = 3; }
        if (s4 > bb) { bb = s4; last = 4; }

        asm volatile("bar.sync 2, 288;" ::: "memory");   // boundaries ready
        asm volatile("bar.sync 3, 288;" ::: "memory");   // s_bp ready

        // ---- backtrace via suffix scan of packed [5]->[5] map compositions
        const int IDMAP = 0 | (1 << 3) | (2 << 6) | (3 << 9) | (4 << 12);
        int wv[16];
        const int tb2 = lane * 16;
#pragma unroll
        for (int u = 0; u < 16; u++) wv[u] = s_bp[tb2 + u];
        if (lane == 0) wv[0] = IDMAP;

        int G = wv[0];
#pragma unroll
        for (int u = 1; u < 16; u++) G = fcompose(G, wv[u]);

        int T = G;
#pragma unroll
        for (int d = 1; d < 32; d <<= 1) {
            int o = __shfl_down_sync(0xffffffffu, T, d);
            T = (lane + d < 32) ? fcompose(T, o) : T;
        }
        int E = __shfl_down_sync(0xffffffffu, T, 1);
        if (lane == 31) E = IDMAP;

        int tag = (E >> (3 * last)) & 7;
        float* po = out + 1 + (size_t)b * S;
        po[tb2 + 15] = (float)tag;
#pragma unroll
        for (int u = 15; u >= 1; u--) {
            tag = (wv[u] >> (3 * tag)) & 7;
            po[tb2 + u - 1] = (float)tag;
        }
        return;
    }

    if (wid == 9) {
        // ========================== numerator ==============================
        const int* lb = labels + b * S;
        float acc = 0.f;
        for (int s2 = lane; s2 < S; s2 += 32) {
            int l0 = lb[s2];
            float term = wts[l0] * em[s2 * L + l0];
            if (s2 + 1 < S) {
                int l1 = lb[s2 + 1];
                term += trans[l0 * L + l1];
            }
            acc += term;
        }
#pragma unroll
        for (int d = 16; d > 0; d >>= 1)
            acc += __shfl_xor_sync(0xffffffffu, acc, d);
        if (lane == 0)
            g_num[b] = acc + start_tr[lb[0]] + end_tr[lb[S - 1]];
        return;
    }

    // ===================== warps 0..7: forward + pass B ====================
    {
        // ---- forward: chunk transfer matrix (scaled prob) -----------------
        const int cj = lane % 5;        // column j
        const int ci = lane / 5;        // row i (>=5 for lanes 25..31)
        const bool act = lane < 25;
        const int b5 = lane - cj;       // 5*i
        const float E0 = ex2f_(trans[0 * L + cj] * LOG2E_F);
        const float E1 = ex2f_(trans[1 * L + cj] * LOG2E_F);
        const float E2 = ex2f_(trans[2 * L + cj] * LOG2E_F);
        const float E3 = ex2f_(trans[3 * L + cj] * LOG2E_F);
        const float E4 = ex2f_(trans[4 * L + cj] * LOG2E_F);

        float m = (act && ci == cj) ? 1.f : 0.f;
        int cexp = 0;
        const int t0 = 1 + 64 * wid;
        const int t1 = (t0 + 64 < S) ? (t0 + 64) : S;

        float fb[8];
#pragma unroll
        for (int u = 0; u < 8; u++) {
            int tt = t0 + u;
            fb[u] = (tt < t1) ? ex2f_(em[tt * 5 + cj] * LOG2E_F) : 1.f;
        }

        for (int tb = t0; tb < t1; tb += 8) {
            float fn[8];
#pragma unroll
            for (int u = 0; u < 8; u++) {
                int tt = tb + 8 + u;
                fn[u] = (tt < t1) ? ex2f_(em[tt * 5 + cj] * LOG2E_F) : 1.f;
            }
#pragma unroll
            for (int u = 0; u < 8; u++) {
                if (tb + u < t1) {
                    float a0 = __shfl_sync(0xffffffffu, m, b5 + 0);
                    float a1 = __shfl_sync(0xffffffffu, m, b5 + 1);
                    float a2 = __shfl_sync(0xffffffffu, m, b5 + 2);
                    float a3 = __shfl_sync(0xffffffffu, m, b5 + 3);
                    float a4 = __shfl_sync(0xffffffffu, m, b5 + 4);
                    float sm = (fmaf(a0, E0, a1 * E1) + fmaf(a2, E2, a3 * E3))
                               + a4 * E4;
                    m = act ? sm * fb[u] : 0.f;
                }
            }
            // renormalize by 2^-k, k = exponent of warp max
            float mx = m;
            mx = fmaxf(mx, __shfl_xor_sync(0xffffffffu, mx, 1));
            mx = fmaxf(mx, __shfl_xor_sync(0xffffffffu, mx, 2));
            mx = fmaxf(mx, __shfl_xor_sync(0xffffffffu, mx, 4));
            mx = fmaxf(mx, __shfl_xor_sync(0xffffffffu, mx, 8));
            mx = fmaxf(mx, __shfl_xor_sync(0xffffffffu, mx, 16));
            int kx = ((__float_as_int(mx) >> 23) & 255) - 127;
            m *= __int_as_float((127 - kx) << 23);
            cexp += kx;
#pragma unroll
            for (int u = 0; u < 8; u++) fb[u] = fn[u];
        }
        if (act) sM[wid * 25 + lane] = m;
        if (lane == 0) sC[wid] = cexp;
        asm volatile("bar.sync 1, 256;" ::: "memory");

        if (wid == 0) {
            // combine: v = alpha0; v <- v * M_c for c=0..7
            const bool aj = lane < 5;
            float v = aj ? ex2f_((start_tr[lane] + em[lane]) * LOG2E_F) : 0.f;
            int ct = 0;
#pragma unroll
            for (int c = 0; c < 8; c++) {
                float a0 = __shfl_sync(0xffffffffu, v, 0);
                float a1 = __shfl_sync(0xffffffffu, v, 1);
                float a2 = __shfl_sync(0xffffffffu, v, 2);
                float a3 = __shfl_sync(0xffffffffu, v, 3);
                float a4 = __shfl_sync(0xffffffffu, v, 4);
                float nv = 0.f;
                if (aj) {
                    const float* Mc = sM + c * 25 + lane;
                    nv = fmaf(a0, Mc[0], fmaf(a1, Mc[5], fmaf(a2, Mc[10],
                         fmaf(a3, Mc[15], a4 * Mc[20]))));
                }
                float mx = nv;
                mx = fmaxf(mx, __shfl_xor_sync(0xffffffffu, mx, 1));
                mx = fmaxf(mx, __shfl_xor_sync(0xffffffffu, mx, 2));
                mx = fmaxf(mx, __shfl_xor_sync(0xffffffffu, mx, 4));
                int kx = ((__float_as_int(mx) >> 23) & 255) - 127;
                v = nv * __int_as_float((127 - kx) << 23);
                ct += sC[c] + kx;
            }
            float r = aj ? v * ex2f_(end_tr[lane] * LOG2E_F) : 0.f;
            r += __shfl_xor_sync(0xffffffffu, r, 1);
            r += __shfl_xor_sync(0xffffffffu, r, 2);
            r += __shfl_xor_sync(0xffffffffu, r, 4);
            if (lane == 0)
                g_logz[b] = ((float)ct + lg2f_(fmaxf(r, 1e-38f))) * LN2_F;
        }
    }

    asm volatile("bar.sync 2, 288;" ::: "memory");   // wait pass-A boundaries

    {
        // ---- pass B: Viterbi chunk with backpointers (exact boundaries) ---
        const int j = lane % 5;
        const float T0 = trans[0 * L + j];
        const float T1 = trans[1 * L + j];
        const float T2 = trans[2 * L + j];
        const float T3 = trans[3 * L + j];
        const float T4 = trans[4 * L + j];
        float v = sBnd[wid * 5 + j];
        const int t0 = 1 + 64 * wid;
        const int t1 = (t0 + 64 < S) ? (t0 + 64) : S;

        float eb[8];
#pragma unroll
        for (int u = 0; u < 8; u++) {
            int tt = t0 + u;
            eb[u] = (tt < t1) ? em[tt * 5 + j] : 0.f;
        }

        for (int tb = t0; tb < t1; tb += 8) {
            float en[8];
#pragma unroll
            for (int u = 0; u < 8; u++) {
                int tt = tb + 8 + u;
                en[u] = (tt < t1) ? em[tt * 5 + j] : 0.f;
            }
#pragma unroll
            for (int u = 0; u < 8; u++) {
                const int tcur = tb + u;
                if (tcur < t1) {
                    float v0 = __shfl_sync(0xffffffffu, v, 0);
                    float v1 = __shfl_sync(0xffffffffu, v, 1);
                    float v2 = __shfl_sync(0xffffffffu, v, 2);
                    float v3 = __shfl_sync(0xffffffffu, v, 3);
                    float v4 = __shfl_sync(0xffffffffu, v, 4);
                    float c0 = v0 + T0, c1 = v1 + T1, c2 = v2 + T2;
                    float c3 = v3 + T3, c4 = v4 + T4;
                    float best = fmaxf(fmaxf(fmaxf(c0, c1), fmaxf(c2, c3)), c4);
                    // first-occurrence argmax (ties -> lowest index)
                    int bp = (c0 == best) ? 0 : (c1 == best) ? 1
                           : (c2 == best) ? 2 : (c3 == best) ? 3 : 4;
                    v = best + eb[u];
                    // pack the 5 canonical bps (lanes 0..4) into one word
                    int b0 = __shfl_sync(0xffffffffu, bp, 0);
                    int b1 = __shfl_sync(0xffffffffu, bp, 1);
                    int b2 = __shfl_sync(0xffffffffu, bp, 2);
                    int b3 = __shfl_sync(0xffffffffu, bp, 3);
                    int b4 = __shfl_sync(0xffffffffu, bp, 4);
                    if (lane == 0)
                        s_bp[tcur] = b0 | (b1 << 3) | (b2 << 6) | (b3 << 9)
                                   | (b4 << 12);
                }
            }
#pragma unroll
            for (int u = 0; u < 8; u++) eb[u] = en[u];
        }
    }

    asm volatile("bar.sync 3, 288;" ::: "memory");   // s_bp complete
}

// ---------------------------------------------------------------------------
// Kernel 3: loss = -sum_b(num_b - logz_b) / (B*S)
// ---------------------------------------------------------------------------
__global__ __launch_bounds__(64) void k_final(float* __restrict__ out) {
    const int t = threadIdx.x;
    float v = g_num[t] - g_logz[t];
#pragma unroll
    for (int d = 16; d > 0; d >>= 1)
        v += __shfl_xor_sync(0xffffffffu, v, d);
    __shared__ float sh[2];
    if ((t & 31) == 0) sh[t >> 5] = v;
    __syncthreads();
    if (t == 0) out[0] = -(sh[0] + sh[1]) * (1.0f / (float)(B * S));
}

// ---------------------------------------------------------------------------
// Launch. Inputs: feats f32, labels i32, mask bool (all ones, unused),
// W_tag f32, b_tag f32, start_trans f32, end_trans f32, trans f32, weights f32.
// Output: [loss, paths(B*S)] as float32.
// ---------------------------------------------------------------------------
extern "C" void kernel_launch(void* const* d_in, const int* in_sizes, int n_in,
                              void* d_out, int out_size) {
    (void)in_sizes; (void)n_in; (void)out_size;
    const float* feats  = (const float*)d_in[0];
    const int*   labels = (const int*)d_in[1];
    const float* W      = (const float*)d_in[3];
    const float* bias   = (const float*)d_in[4];
    const float* st     = (const float*)d_in[5];
    const float* en     = (const float*)d_in[6];
    const float* tr     = (const float*)d_in[7];
    const float* wt     = (const float*)d_in[8];
    float* out = (float*)d_out;

    k_emis<<<1024, 256>>>(feats, W, bias);
    k_crf<<<B, 320>>>(labels, st, en, tr, wt, out);
    k_final<<<1, 64>>>(out);
}

// round 11
// speedup vs baseline: 1.5735x; 1.0236x over previous
#include <cuda_runtime.h>
#include <math.h>

#define B 64
#define S 512
#define H 1024
#define L 5

#define LOG2E_F 1.4426950408889634f
#define LN2_F   0.6931471805599453f

// Scratch (static device globals — allocation-free per harness rules)
__device__ float g_emis[B * S * L];
__device__ float g_num[B];
__device__ float g_logz[B];

__device__ __forceinline__ float ex2f_(float x) {
    float r; asm("ex2.approx.ftz.f32 %0, %1;" : "=f"(r) : "f"(x)); return r;
}
__device__ __forceinline__ float lg2f_(float x) {
    float r; asm("lg2.approx.f32 %0, %1;" : "=f"(r) : "f"(x)); return r;
}

__device__ __forceinline__ void dot4(float& a, const float4& v, const float4& wv) {
    a = fmaf(v.x, wv.x, fmaf(v.y, wv.y, fmaf(v.z, wv.z, fmaf(v.w, wv.w, a))));
}

// ---------------------------------------------------------------------------
// Kernel 1: emissions = relu(feats @ W + b)
// Warp owns 4 rows, lane owns float4 slice (lane + 32*i): contiguous 512B
// warp LDGs. Prefetch distance 2 -> 8 LDG.128 in flight per warp.
// W transposed in smem (LDS.128, 16B lane stride, conflict-free).
// 1024 blocks x 256 threads, min 3 blocks/SM.
// ---------------------------------------------------------------------------
__global__ __launch_bounds__(256, 3) void k_emis(const float* __restrict__ feats,
                                                 const float* __restrict__ Wg,
                                                 const float* __restrict__ bias) {
    __shared__ float sWT[5 * 1024];   // sWT[l*1024 + k] = W[k][l]
    const int t = threadIdx.x;
    for (int i = t; i < H * L; i += 256) {
        const int k = i / 5, l = i - 5 * k;
        sWT[l * 1024 + k] = Wg[i];
    }
    __syncthreads();

    const int lane = t & 31, w = t >> 5;
    const int row0 = blockIdx.x * 32 + w * 4;
    const float4* p0 = (const float4*)(feats + (size_t)(row0 + 0) * H);
    const float4* p1 = (const float4*)(feats + (size_t)(row0 + 1) * H);
    const float4* p2 = (const float4*)(feats + (size_t)(row0 + 2) * H);
    const float4* p3 = (const float4*)(feats + (size_t)(row0 + 3) * H);

    float acc[4][5];
#pragma unroll
    for (int r = 0; r < 4; r++)
#pragma unroll
        for (int l = 0; l < 5; l++) acc[r][l] = 0.f;

    // prefetch distance 2
    float4 xa0 = p0[lane],      xa1 = p1[lane],      xa2 = p2[lane],      xa3 = p3[lane];
    float4 xb0 = p0[lane + 32], xb1 = p1[lane + 32], xb2 = p2[lane + 32], xb3 = p3[lane + 32];

#pragma unroll
    for (int i = 0; i < 8; i++) {
        float4 xc0, xc1, xc2, xc3;
        if (i < 6) {
            const int idx = lane + 32 * (i + 2);
            xc0 = p0[idx]; xc1 = p1[idx]; xc2 = p2[idx]; xc3 = p3[idx];
        }
        const int ko = (lane + 32 * i) * 4;
        const float4 w0 = *(const float4*)(sWT + 0 * 1024 + ko);
        const float4 w1 = *(const float4*)(sWT + 1 * 1024 + ko);
        const float4 w2 = *(const float4*)(sWT + 2 * 1024 + ko);
        const float4 w3 = *(const float4*)(sWT + 3 * 1024 + ko);
        const float4 w4 = *(const float4*)(sWT + 4 * 1024 + ko);

        dot4(acc[0][0], xa0, w0); dot4(acc[0][1], xa0, w1);
        dot4(acc[0][2], xa0, w2); dot4(acc[0][3], xa0, w3);
        dot4(acc[0][4], xa0, w4);
        dot4(acc[1][0], xa1, w0); dot4(acc[1][1], xa1, w1);
        dot4(acc[1][2], xa1, w2); dot4(acc[1][3], xa1, w3);
        dot4(acc[1][4], xa1, w4);
        dot4(acc[2][0], xa2, w0); dot4(acc[2][1], xa2, w1);
        dot4(acc[2][2], xa2, w2); dot4(acc[2][3], xa2, w3);
        dot4(acc[2][4], xa2, w4);
        dot4(acc[3][0], xa3, w0); dot4(acc[3][1], xa3, w1);
        dot4(acc[3][2], xa3, w2); dot4(acc[3][3], xa3, w3);
        dot4(acc[3][4], xa3, w4);

        xa0 = xb0; xa1 = xb1; xa2 = xb2; xa3 = xb3;
        if (i < 6) { xb0 = xc0; xb1 = xc1; xb2 = xc2; xb3 = xc3; }
    }

    // butterfly reduce all 20 accumulators over the 32 lanes
#pragma unroll
    for (int r = 0; r < 4; r++)
#pragma unroll
        for (int l = 0; l < 5; l++) {
#pragma unroll
            for (int d = 16; d > 0; d >>= 1)
                acc[r][l] += __shfl_xor_sync(0xffffffffu, acc[r][l], d);
        }

    // lane m (< 20) writes output element row0*5 + m  (m = r*5 + l)
    float val = 0.f;
#pragma unroll
    for (int r = 0; r < 4; r++)
#pragma unroll
        for (int l = 0; l < 5; l++)
            if (lane == r * 5 + l) val = acc[r][l];
    if (lane < 20)
        g_emis[(size_t)row0 * 5 + lane] = fmaxf(val + bias[lane % 5], 0.f);
}

// packed [5]->[5] map composition: returns f∘g (g applied first)
__device__ __forceinline__ int fcompose(int f, int g) {
    int r = 0;
#pragma unroll
    for (int x = 0; x < 5; x++) {
        int gx = (g >> (3 * x)) & 7;
        int fx = (f >> (3 * gx)) & 7;
        r |= fx << (3 * x);
    }
    return r;
}

// ---------------------------------------------------------------------------
// Kernel 2: CRF. Grid = 128 blocks x 288 threads (one wave, own SM each):
//   blocks 0..63  (batch b)    : warp 8 = pass-A Viterbi (value-only serial,
//       bit-exact) with warps 0..7 ASLEEP at __syncthreads (no contention);
//       then warps 0..7 = pass-B backpointer chunks from exact boundaries;
//       then warp 8 = compose-scan backtrace.
//   blocks 64..127 (batch b-64): warps 0..7 = forward chunk matrices ->
//       bar1 -> warp 0 combine (logZ); warp 8 = gold-path numerator.
// ---------------------------------------------------------------------------
__global__ __launch_bounds__(288) void k_crf(const int* __restrict__ labels,
                                             const float* __restrict__ start_tr,
                                             const float* __restrict__ end_tr,
                                             const float* __restrict__ trans,
                                             const float* __restrict__ wts,
                                             float* __restrict__ out) {
    const int bid = blockIdx.x;
    const int tid = threadIdx.x;
    const int wid = tid >> 5;
    const int lane = tid & 31;

    if (bid < 64) {
        // ==================== Viterbi block (batch = bid) ==================
        const int b = bid;
        const float* em = g_emis + (size_t)b * (S * L);
        __shared__ int   s_bp[S];
        __shared__ float sBnd[8 * 5];   // exact Viterbi state at t = 64*c

        if (wid == 8) {
            // ============ pass A: value-only Viterbi (serial, exact) =======
            const int j = lane % 5;
            const float T0 = trans[0 * L + j];
            const float T1 = trans[1 * L + j];
            const float T2 = trans[2 * L + j];
            const float T3 = trans[3 * L + j];
            const float T4 = trans[4 * L + j];
            float v = start_tr[j] + em[j];
            if (lane < 5) sBnd[lane] = v;

            float eb[8];
#pragma unroll
            for (int u = 0; u < 8; u++) eb[u] = em[(1 + u) * 5 + j];

            for (int tb = 1; tb < S; tb += 8) {
                float en[8];
#pragma unroll
                for (int u = 0; u < 8; u++) {
                    int tt = tb + 8 + u;
                    en[u] = (tt < S) ? em[tt * 5 + j] : 0.f;
                }
#pragma unroll
                for (int u = 0; u < 8; u++) {
                    const int tcur = tb + u;
                    if (tcur < S) {
                        float v0 = __shfl_sync(0xffffffffu, v, 0);
                        float v1 = __shfl_sync(0xffffffffu, v, 1);
                        float v2 = __shfl_sync(0xffffffffu, v, 2);
                        float v3 = __shfl_sync(0xffffffffu, v, 3);
                        float v4 = __shfl_sync(0xffffffffu, v, 4);
                        float c0 = v0 + T0, c1 = v1 + T1, c2 = v2 + T2;
                        float c3 = v3 + T3, c4 = v4 + T4;
                        float best = fmaxf(fmaxf(fmaxf(c0, c1), fmaxf(c2, c3)), c4);
                        v = best + eb[u];
                        if (((tcur & 63) == 0) && lane < 5)
                            sBnd[(tcur >> 6) * 5 + lane] = v;
                    }
                }
#pragma unroll
                for (int u = 0; u < 8; u++) eb[u] = en[u];
            }

            // final tag: first-occurrence argmax over (v + end)
            float sc = v + end_tr[j];
            float s0 = __shfl_sync(0xffffffffu, sc, 0);
            float s1 = __shfl_sync(0xffffffffu, sc, 1);
            float s2 = __shfl_sync(0xffffffffu, sc, 2);
            float s3 = __shfl_sync(0xffffffffu, sc, 3);
            float s4 = __shfl_sync(0xffffffffu, sc, 4);
            int last = 0; float bb = s0;
            if (s1 > bb) { bb = s1; last = 1; }
            if (s2 > bb) { bb = s2; last = 2; }
            if (s3 > bb) { bb = s3; last = 3; }
            if (s4 > bb) { bb = s4; last = 4; }

            __syncthreads();   // boundaries ready -> wake warps 0..7
            __syncthreads();   // s_bp complete

            // ---- backtrace via suffix scan of packed [5]->[5] maps --------
            const int IDMAP = 0 | (1 << 3) | (2 << 6) | (3 << 9) | (4 << 12);
            int wv[16];
            const int tb2 = lane * 16;
#pragma unroll
            for (int u = 0; u < 16; u++) wv[u] = s_bp[tb2 + u];
            if (lane == 0) wv[0] = IDMAP;

            int G = wv[0];
#pragma unroll
            for (int u = 1; u < 16; u++) G = fcompose(G, wv[u]);

            int T = G;
#pragma unroll
            for (int d = 1; d < 32; d <<= 1) {
                int o = __shfl_down_sync(0xffffffffu, T, d);
                T = (lane + d < 32) ? fcompose(T, o) : T;
            }
            int E = __shfl_down_sync(0xffffffffu, T, 1);
            if (lane == 31) E = IDMAP;

            int tag = (E >> (3 * last)) & 7;
            float* po = out + 1 + (size_t)b * S;
            po[tb2 + 15] = (float)tag;
#pragma unroll
            for (int u = 15; u >= 1; u--) {
                tag = (wv[u] >> (3 * tag)) & 7;
                po[tb2 + u - 1] = (float)tag;
            }
        } else {
            // warps 0..7: sleep until pass-A boundaries are ready
            __syncthreads();

            // ---- pass B: Viterbi chunk with backpointers ------------------
            const int j = lane % 5;
            const float T0 = trans[0 * L + j];
            const float T1 = trans[1 * L + j];
            const float T2 = trans[2 * L + j];
            const float T3 = trans[3 * L + j];
            const float T4 = trans[4 * L + j];
            float v = sBnd[wid * 5 + j];
            const int t0 = 1 + 64 * wid;
            const int t1 = (t0 + 64 < S) ? (t0 + 64) : S;

            float eb[8];
#pragma unroll
            for (int u = 0; u < 8; u++) {
                int tt = t0 + u;
                eb[u] = (tt < t1) ? em[tt * 5 + j] : 0.f;
            }

            for (int tb = t0; tb < t1; tb += 8) {
                float en[8];
#pragma unroll
                for (int u = 0; u < 8; u++) {
                    int tt = tb + 8 + u;
                    en[u] = (tt < t1) ? em[tt * 5 + j] : 0.f;
                }
#pragma unroll
                for (int u = 0; u < 8; u++) {
                    const int tcur = tb + u;
                    if (tcur < t1) {
                        float v0 = __shfl_sync(0xffffffffu, v, 0);
                        float v1 = __shfl_sync(0xffffffffu, v, 1);
                        float v2 = __shfl_sync(0xffffffffu, v, 2);
                        float v3 = __shfl_sync(0xffffffffu, v, 3);
                        float v4 = __shfl_sync(0xffffffffu, v, 4);
                        float c0 = v0 + T0, c1 = v1 + T1, c2 = v2 + T2;
                        float c3 = v3 + T3, c4 = v4 + T4;
                        float best = fmaxf(fmaxf(fmaxf(c0, c1), fmaxf(c2, c3)), c4);
                        int bp = (c0 == best) ? 0 : (c1 == best) ? 1
                               : (c2 == best) ? 2 : (c3 == best) ? 3 : 4;
                        v = best + eb[u];
                        int b0 = __shfl_sync(0xffffffffu, bp, 0);
                        int b1 = __shfl_sync(0xffffffffu, bp, 1);
                        int b2 = __shfl_sync(0xffffffffu, bp, 2);
                        int b3 = __shfl_sync(0xffffffffu, bp, 3);
                        int b4 = __shfl_sync(0xffffffffu, bp, 4);
                        if (lane == 0)
                            s_bp[tcur] = b0 | (b1 << 3) | (b2 << 6) | (b3 << 9)
                                       | (b4 << 12);
                    }
                }
#pragma unroll
                for (int u = 0; u < 8; u++) eb[u] = en[u];
            }
            __syncthreads();   // s_bp complete -> backtrace may proceed
        }
        return;
    }

    // ===================== forward + numerator block =======================
    const int b = bid - 64;
    const float* em = g_emis + (size_t)b * (S * L);
    __shared__ float sM[8 * 25];
    __shared__ int   sC[8];

    if (wid == 8) {
        // ========================== numerator ==============================
        const int* lb = labels + b * S;
        float acc = 0.f;
        for (int s2 = lane; s2 < S; s2 += 32) {
            int l0 = lb[s2];
            float term = wts[l0] * em[s2 * L + l0];
            if (s2 + 1 < S) {
                int l1 = lb[s2 + 1];
                term += trans[l0 * L + l1];
            }
            acc += term;
        }
#pragma unroll
        for (int d = 16; d > 0; d >>= 1)
            acc += __shfl_xor_sync(0xffffffffu, acc, d);
        if (lane == 0)
            g_num[b] = acc + start_tr[lb[0]] + end_tr[lb[S - 1]];
        return;
    }

    {
        // ---- forward: chunk transfer matrix (scaled prob) -----------------
        const int cj = lane % 5;        // column j
        const int ci = lane / 5;        // row i (>=5 for lanes 25..31)
        const bool act = lane < 25;
        const int b5 = lane - cj;       // 5*i
        const float E0 = ex2f_(trans[0 * L + cj] * LOG2E_F);
        const float E1 = ex2f_(trans[1 * L + cj] * LOG2E_F);
        const float E2 = ex2f_(trans[2 * L + cj] * LOG2E_F);
        const float E3 = ex2f_(trans[3 * L + cj] * LOG2E_F);
        const float E4 = ex2f_(trans[4 * L + cj] * LOG2E_F);

        float m = (act && ci == cj) ? 1.f : 0.f;
        int cexp = 0;
        const int t0 = 1 + 64 * wid;
        const int t1 = (t0 + 64 < S) ? (t0 + 64) : S;

        float fb[8];
#pragma unroll
        for (int u = 0; u < 8; u++) {
            int tt = t0 + u;
            fb[u] = (tt < t1) ? ex2f_(em[tt * 5 + cj] * LOG2E_F) : 1.f;
        }

        for (int tb = t0; tb < t1; tb += 8) {
            float fn[8];
#pragma unroll
            for (int u = 0; u < 8; u++) {
                int tt = tb + 8 + u;
                fn[u] = (tt < t1) ? ex2f_(em[tt * 5 + cj] * LOG2E_F) : 1.f;
            }
#pragma unroll
            for (int u = 0; u < 8; u++) {
                if (tb + u < t1) {
                    float a0 = __shfl_sync(0xffffffffu, m, b5 + 0);
                    float a1 = __shfl_sync(0xffffffffu, m, b5 + 1);
                    float a2 = __shfl_sync(0xffffffffu, m, b5 + 2);
                    float a3 = __shfl_sync(0xffffffffu, m, b5 + 3);
                    float a4 = __shfl_sync(0xffffffffu, m, b5 + 4);
                    float sm = (fmaf(a0, E0, a1 * E1) + fmaf(a2, E2, a3 * E3))
                               + a4 * E4;
                    m = act ? sm * fb[u] : 0.f;
                }
            }
            // renormalize by 2^-k, k = exponent of warp max
            float mx = m;
            mx = fmaxf(mx, __shfl_xor_sync(0xffffffffu, mx, 1));
            mx = fmaxf(mx, __shfl_xor_sync(0xffffffffu, mx, 2));
            mx = fmaxf(mx, __shfl_xor_sync(0xffffffffu, mx, 4));
            mx = fmaxf(mx, __shfl_xor_sync(0xffffffffu, mx, 8));
            mx = fmaxf(mx, __shfl_xor_sync(0xffffffffu, mx, 16));
            int kx = ((__float_as_int(mx) >> 23) & 255) - 127;
            m *= __int_as_float((127 - kx) << 23);
            cexp += kx;
#pragma unroll
            for (int u = 0; u < 8; u++) fb[u] = fn[u];
        }
        if (act) sM[wid * 25 + lane] = m;
        if (lane == 0) sC[wid] = cexp;
        asm volatile("bar.sync 1, 256;" ::: "memory");

        if (wid == 0) {
            // combine: v = alpha0; v <- v * M_c for c=0..7
            const bool aj = lane < 5;
            float v = aj ? ex2f_((start_tr[lane] + em[lane]) * LOG2E_F) : 0.f;
            int ct = 0;
#pragma unroll
            for (int c = 0; c < 8; c++) {
                float a0 = __shfl_sync(0xffffffffu, v, 0);
                float a1 = __shfl_sync(0xffffffffu, v, 1);
                float a2 = __shfl_sync(0xffffffffu, v, 2);
                float a3 = __shfl_sync(0xffffffffu, v, 3);
                float a4 = __shfl_sync(0xffffffffu, v, 4);
                float nv = 0.f;
                if (aj) {
                    const float* Mc = sM + c * 25 + lane;
                    nv = fmaf(a0, Mc[0], fmaf(a1, Mc[5], fmaf(a2, Mc[10],
                         fmaf(a3, Mc[15], a4 * Mc[20]))));
                }
                float mx = nv;
                mx = fmaxf(mx, __shfl_xor_sync(0xffffffffu, mx, 1));
                mx = fmaxf(mx, __shfl_xor_sync(0xffffffffu, mx, 2));
                mx = fmaxf(mx, __shfl_xor_sync(0xffffffffu, mx, 4));
                int kx = ((__float_as_int(mx) >> 23) & 255) - 127;
                v = nv * __int_as_float((127 - kx) << 23);
                ct += sC[c] + kx;
            }
            float r = aj ? v * ex2f_(end_tr[lane] * LOG2E_F) : 0.f;
            r += __shfl_xor_sync(0xffffffffu, r, 1);
            r += __shfl_xor_sync(0xffffffffu, r, 2);
            r += __shfl_xor_sync(0xffffffffu, r, 4);
            if (lane == 0)
                g_logz[b] = ((float)ct + lg2f_(fmaxf(r, 1e-38f))) * LN2_F;
        }
    }
}

// ---------------------------------------------------------------------------
// Kernel 3: loss = -sum_b(num_b - logz_b) / (B*S)
// ---------------------------------------------------------------------------
__global__ __launch_bounds__(64) void k_final(float* __restrict__ out) {
    const int t = threadIdx.x;
    float v = g_num[t] - g_logz[t];
#pragma unroll
    for (int d = 16; d > 0; d >>= 1)
        v += __shfl_xor_sync(0xffffffffu, v, d);
    __shared__ float sh[2];
    if ((t & 31) == 0) sh[t >> 5] = v;
    __syncthreads();
    if (t == 0) out[0] = -(sh[0] + sh[1]) * (1.0f / (float)(B * S));
}

// ---------------------------------------------------------------------------
// Launch. Inputs: feats f32, labels i32, mask bool (all ones, unused),
// W_tag f32, b_tag f32, start_trans f32, end_trans f32, trans f32, weights f32.
// Output: [loss, paths(B*S)] as float32.
// ---------------------------------------------------------------------------
extern "C" void kernel_launch(void* const* d_in, const int* in_sizes, int n_in,
                              void* d_out, int out_size) {
    (void)in_sizes; (void)n_in; (void)out_size;
    const float* feats  = (const float*)d_in[0];
    const int*   labels = (const int*)d_in[1];
    const float* W      = (const float*)d_in[3];
    const float* bias   = (const float*)d_in[4];
    const float* st     = (const float*)d_in[5];
    const float* en     = (const float*)d_in[6];
    const float* tr     = (const float*)d_in[7];
    const float* wt     = (const float*)d_in[8];
    float* out = (float*)d_out;

    k_emis<<<1024, 256>>>(feats, W, bias);
    k_crf<<<128, 288>>>(labels, st, en, tr, wt, out);
    k_final<<<1, 64>>>(out);
}